// round 12
// baseline (speedup 1.0000x reference)
#include <cuda_runtime.h>
#include <math.h>

// NUFFT layer — fully analytic (round-8 math). Round-11/12: ZERO cross-block
// communication. Each block redundantly computes its batch's full mode sums
// (A[m],B[m], m<64 — modes >=64 carry e^{-7.9e-3 m^2} < 1e-14 relative) over
// all 1024 particles, then outputs its own 128-particle slice directly.
// No __device__ state, no grid/cluster barrier, only __syncthreads.
// (Round-11 bench was an infra failure; identical design re-submitted.)

#define NMODES 64
#define NBATCH 8
#define NPART  1024
#define GRIDB  64            // 8 batches x 8 blocks
#define TPB    512

#define TWO_PI_F 6.2831853071795864769f

// complex helpers (FMA forms)
#define CMUL(rr, ri, ar, ai, br, bi) \
    do { rr = fmaf((ar), (br), -(ai) * (bi)); ri = fmaf((ar), (bi), (ai) * (br)); } while (0)
#define CSQ(rr, ri, ar, ai) \
    do { rr = fmaf((ar), (ar), -(ai) * (ai)); ri = 2.f * (ar) * (ai); } while (0)

__global__ __launch_bounds__(TPB, 1) void k_all(
    const float* __restrict__ x,
    const float* __restrict__ sigma_var,
    const float* __restrict__ shift0,
    const float* __restrict__ shift1,
    const float* __restrict__ amp0,
    const float* __restrict__ amp1,
    float* __restrict__ out)
{
    const int bb   = blockIdx.x;
    const int tid  = threadIdx.x;
    const int w    = tid >> 5;
    const int lane = tid & 31;
    const int b    = bb >> 3;             // batch
    const int sub  = bb & 7;              // output slice (128 particles)

    __shared__ float4 sstep[NPART];               // (z, z8) per batch particle (16KB)
    __shared__ float  spart[16][2 * NMODES + 1];  // per-warp partials (+1 pad)
    __shared__ float4 tabU[NMODES];               // (A, B, U0, U1)
    __shared__ float2 tabV[NMODES];               // (V0, V1) with-deconv (edge f)
    __shared__ float  sf0[12], sf1[12];           // edge field values

    // ---- Phase A: full mode sums, warp w covers particles w*64..w*64+63 ----
    {
        const int p0 = b * NPART + w * 64 + lane;
        const float xv0 = x[p0];
        const float xv1 = x[p0 + 32];

        float z0r, z0i, z1r, z1i;
        __sincosf(TWO_PI_F * (xv0 - rintf(xv0)), &z0i, &z0r);
        __sincosf(TWO_PI_F * (xv1 - rintf(xv1)), &z1i, &z1r);
        float t0r, t0i, z08r, z08i, t1r, t1i, z18r, z18i;
        CSQ(t0r, t0i, z0r, z0i);  CSQ(z08r, z08i, t0r, t0i); CSQ(z08r, z08i, z08r, z08i);
        CSQ(t1r, t1i, z1r, z1i);  CSQ(z18r, z18i, t1r, t1i); CSQ(z18r, z18i, z18r, z18i);
        sstep[w * 64 + lane]      = make_float4(z0r, z0i, z08r, z08i);
        sstep[w * 64 + 32 + lane] = make_float4(z1r, z1i, z18r, z18i);

        float b0r = 1.f, b0i = 0.f, b1r = 1.f, b1i = 0.f;   // z^{8*chunk}
#pragma unroll
        for (int chunk = 0; chunk < 8; ++chunk) {
            float c0r = b0r, c0i = b0i, c1r = b1r, c1i = b1i;
            float v[16];
#pragma unroll
            for (int j = 0; j < 8; ++j) {
                v[2 * j]     = c0r + c1r;
                v[2 * j + 1] = c0i + c1i;
                float n0r = fmaf(c0r, z0r, -c0i * z0i);
                float n0i = fmaf(c0i, z0r,  c0r * z0i);
                float n1r = fmaf(c1r, z1r, -c1i * z1i);
                float n1i = fmaf(c1i, z1r,  c1r * z1i);
                c0r = n0r; c0i = n0i; c1r = n1r; c1i = n1i;
            }
#pragma unroll
            for (int s = 0; s < 4; ++s) {                   // 15-shfl halving
                const int  half = 8 >> s;
                const bool up   = (lane >> s) & 1;
#pragma unroll
                for (int k = 0; k < half; ++k) {
                    float send = up ? v[k] : v[k + half];
                    float recv = __shfl_xor_sync(0xffffffffu, send, 1 << s);
                    v[k] = (up ? v[k + half] : v[k]) + recv;
                }
            }
            v[0] += __shfl_xor_sync(0xffffffffu, v[0], 16);
            if (lane < 16) {
                const int r = __brev(lane) >> 28;           // bitrev4
                const int m = chunk * 8 + (r >> 1);
                spart[w][(r & 1) * NMODES + m] = v[0];
            }
            b0r = c0r; b0i = c0i;                           // base advanced by z^8
            b1r = c1r; b1i = c1i;
        }
    }
    __syncthreads();

    // ---- reduce 16 warp-partials + spectral multiplier tables -------------
    if (tid < NMODES) {
        const int m = tid;
        float A = 0.f, B = 0.f;
#pragma unroll
        for (int w2 = 0; w2 < 16; ++w2) {
            A += spart[w2][m];
            B += spart[w2][NMODES + m];
        }
        const double TWO_PI_D = 6.283185307179586476925286766559;
        const double taud  = 12.0 / ((TWO_PI_D * 2001.0) * (TWO_PI_D * 2001.0));
        const float TAUF     = (float)taud;
        const float SQPIOTAU = (float)sqrt(3.14159265358979323846 / taud);
        const float s_   = sigma_var[0];
        const float q0   = 25.f * shift0[0] * shift0[0];
        const float q1   = 25.f * shift1[0] * shift1[0];
        const float FOURPI = 12.566370614359172f;
        float kk = TWO_PI_F * (float)m;
        float K2 = kk * kk;
        float fold = (m == 0) ? 1.f : 2.f;
        float base0 = fold * (-amp0[0]) * FOURPI / (K2 + q0);
        float inv  = 1.f / (K2 + q1);
        float base1 = fold * amp1[0] * FOURPI * inv * inv;
        float eg = __expf(-0.5f * s_ * s_ * K2);
        float eU = TWO_PI_F * eg;                 // window x deconv = 2*pi exactly
        float eV = SQPIOTAU * __expf((TAUF - 0.5f * s_ * s_) * K2);
        tabU[m] = make_float4(A, B, base0 * eU, base1 * eU);
        tabV[m] = make_float2(base0 * eV, base1 * eV);
    }
    __syncthreads();

    // ---- edge field: f (with deconv) at grid {0..5, 1995..2000} -----------
    if (tid < 64) {
        const int e = tid >> 2;                   // 0..15 (12 used)
        const int q = tid & 3;
        const int g = (e < 6) ? e : (1995 + (e - 6));

        const float C_HI = (float)(1.0 / 2001.0);
        const float C_LO = (float)(1.0 / 2001.0 - (double)((float)(1.0 / 2001.0)));
        const float gf     = (float)g;
        const float phi_hi = gf * C_HI;
        const float phi_lo = fmaf(gf, C_HI, -phi_hi) + gf * C_LO;

        float sw_, cw_;
        __sincosf(TWO_PI_F * ((phi_hi - rintf(phi_hi)) + phi_lo), &sw_, &cw_);
        float zr, zi;
        if (q == 0) { zr = 1.f; zi = 0.f; }
        else {
            float m0f = (float)(16 * q);
            float hi2 = m0f * phi_hi;
            float lo2 = fmaf(m0f, phi_hi, -hi2);
            float f   = (hi2 - rintf(hi2)) + (lo2 + m0f * phi_lo);
            __sincosf(TWO_PI_F * (f - rintf(f)), &zi, &zr);
        }
        float acc0 = 0.f, acc1 = 0.f;
#pragma unroll
        for (int j = 0; j < 16; ++j) {
            const int m = 16 * q + j;
            float4 t4 = tabU[m];                  // A, B
            float2 v2 = tabV[m];                  // V0, V1
            float tt = fmaf(t4.x, zr, t4.y * zi);
            acc0 = fmaf(v2.x, tt, acc0);
            acc1 = fmaf(v2.y, tt, acc1);
            float nzr = fmaf(zr, cw_, -zi * sw_);
            float nzi = fmaf(zi, cw_,  zr * sw_);
            zr = nzr; zi = nzi;
        }
        acc0 += __shfl_xor_sync(0xffffffffu, acc0, 1);
        acc0 += __shfl_xor_sync(0xffffffffu, acc0, 2);
        acc1 += __shfl_xor_sync(0xffffffffu, acc1, 1);
        acc1 += __shfl_xor_sync(0xffffffffu, acc1, 2);
        if (q == 0 && e < 12) { sf0[e] = acc0; sf1[e] = acc1; }
    }
    __syncthreads();

    // ---- output: 4 threads/particle, 16-mode chains, bases via FMA --------
    {
        const int s  = tid >> 2;                  // 0..127
        const int q  = tid & 3;
        const int pl = sub * 128 + s;             // batch-local particle
        const int p  = b * NPART + pl;

        float4 st = sstep[pl];
        const float zr = st.x, zi = st.y, z8r = st.z, z8i = st.w;
        float z16r, z16i, z32r, z32i;
        CSQ(z16r, z16i, z8r,  z8i);
        CSQ(z32r, z32i, z16r, z16i);
        float b1r = (q & 1) ? z16r : 1.f, b1i = (q & 1) ? z16i : 0.f;
        float b2r = (q & 2) ? z32r : 1.f, b2i = (q & 2) ? z32i : 0.f;
        float cr, ci;                             // base = z^{16q}
        CMUL(cr, ci, b1r, b1i, b2r, b2i);

        float acc0 = 0.f, acc1 = 0.f;
#pragma unroll
        for (int j = 0; j < 16; ++j) {
            float4 t4 = tabU[16 * q + j];
            float tt = fmaf(t4.x, cr, t4.y * ci);
            acc0 = fmaf(t4.z, tt, acc0);
            acc1 = fmaf(t4.w, tt, acc1);
            float nr = fmaf(cr, zr, -ci * zi);
            float ni = fmaf(ci, zr,  cr * zi);
            cr = nr; ci = ni;
        }
        acc0 += __shfl_xor_sync(0xffffffffu, acc0, 1);
        acc0 += __shfl_xor_sync(0xffffffffu, acc0, 2);
        acc1 += __shfl_xor_sync(0xffffffffu, acc1, 1);
        acc1 += __shfl_xor_sync(0xffffffffu, acc1, 2);

        if (q == 0) {
            const float xv = x[p];
            // wrap corrections (reference clamps; Poisson periodizes)
            const double TWO_PI_D = 6.283185307179586476925286766559;
            const float TAUF    = (float)(12.0 / ((TWO_PI_D * 2001.0) * (TWO_PI_D * 2001.0)));
            const float inv4tau = 1.f / (4.f * TAUF);
            const float invN    = (float)(1.0 / 2001.0);
            const int m0 = __float2int_rn(xv * 2001.0f);
            if (m0 <= 6) {
#pragma unroll
                for (int j = 1; j <= 6; ++j) {    // phantom n = -j -> grid 2001-j
                    float d = xv + (float)j * invN;
                    float wgt = invN * __expf(-d * d * inv4tau);
                    acc0 -= wgt * sf0[12 - j];
                    acc1 -= wgt * sf1[12 - j];
                }
            }
            if (m0 >= 1994) {
#pragma unroll
                for (int j = 0; j <= 5; ++j) {    // phantom n = 2001+j -> grid j
                    float d = xv - 1.f - (float)j * invN;
                    float wgt = invN * __expf(-d * d * inv4tau);
                    acc0 -= wgt * sf0[j];
                    acc1 -= wgt * sf1[j];
                }
            }
            out[2 * p]     = acc0;
            out[2 * p + 1] = acc1;
        }
    }
}

// ---------------------------------------------------------------------------
extern "C" void kernel_launch(void* const* d_in, const int* in_sizes, int n_in,
                              void* d_out, int out_size)
{
    (void)in_sizes; (void)n_in; (void)out_size;
    k_all<<<GRIDB, TPB>>>((const float*)d_in[0], (const float*)d_in[1],
                          (const float*)d_in[2], (const float*)d_in[3],
                          (const float*)d_in[4], (const float*)d_in[5],
                          (float*)d_out);
}

// round 14
// speedup vs baseline: 1.4398x; 1.4398x over previous
#include <cuda_runtime.h>
#include <math.h>

// NUFFT layer — fully analytic (round-8 math), round-9 cluster structure,
// NMODES 112 -> 48 (mode 47 ~ e^{-17.4} = 3e-8 relative).
// Round-14 fix: edge-field guard back to tid<64 (WHOLE warps) — round-13's
// tid<48 ran __shfl_xor_sync(full mask) with half of warp 1 inactive -> hang.

#define NMODES 48
#define NBATCH 8
#define NPART  1024
#define CLUST  8
#define GRIDB  (NBATCH * CLUST)   // 64
#define TPB    512

__device__ float g_part[NBATCH][2 * NMODES][CLUST];   // [b][A|B x mode][rank]

#define TWO_PI_F 6.2831853071795864769f

#define CMUL(rr, ri, ar, ai, br, bi) \
    do { rr = fmaf((ar), (br), -(ai) * (bi)); ri = fmaf((ar), (bi), (ai) * (br)); } while (0)
#define CSQ(rr, ri, ar, ai) \
    do { rr = fmaf((ar), (ar), -(ai) * (ai)); ri = 2.f * (ar) * (ai); } while (0)

__device__ __forceinline__ float frac_mx(float m, float x)
{   // frac(m*x) in ~[-0.5,0.5]; exact Dekker split (m <= 44 < 2^7, x fp32)
    float hi = m * x;
    float lo = fmaf(m, x, -hi);
    return (hi - rintf(hi)) + lo;
}

__global__ __launch_bounds__(TPB, 1) __cluster_dims__(CLUST, 1, 1)
void k_fused(
    const float* __restrict__ x,
    const float* __restrict__ sigma_var,
    const float* __restrict__ shift0,
    const float* __restrict__ shift1,
    const float* __restrict__ amp0,
    const float* __restrict__ amp1,
    float* __restrict__ out)
{
    const int b    = blockIdx.x >> 3;     // batch
    const int rank = blockIdx.x & 7;      // rank within cluster
    const int tid  = threadIdx.x;
    const int w    = tid >> 5;
    const int lane = tid & 31;

    __shared__ float  rowsum[2 * NMODES];
    __shared__ float4 tabU[NMODES];       // (A, B, U0, U1)
    __shared__ float2 tabV[NMODES];       // (V0, V1) with-deconv (edge f)
    __shared__ float  sf0[12], sf1[12];   // edge field at grid {0..5,1995..2000}

    // ---- Phase A: 12 warps x 4 modes (4w..4w+3), 4 particles/lane --------
    if (w < 12) {
        const float m4 = (float)(4 * w);
        float v[8];
#pragma unroll
        for (int k = 0; k < 8; ++k) v[k] = 0.f;

#pragma unroll
        for (int pp = 0; pp < 4; ++pp) {
            const float xv = x[b * NPART + rank * 128 + pp * 32 + lane];
            float zr, zi;                             // z = e^{2*pi*i*x}
            __sincosf(TWO_PI_F * (xv - rintf(xv)), &zi, &zr);
            float cr, ci;                             // base = z^{4w} (exact)
            if (w == 0) { cr = 1.f; ci = 0.f; }
            else        { __sincosf(TWO_PI_F * frac_mx(m4, xv), &ci, &cr); }
#pragma unroll
            for (int j = 0; j < 4; ++j) {
                v[2 * j]     += cr;
                v[2 * j + 1] += ci;
                float nr = fmaf(cr, zr, -ci * zi);
                float ni = fmaf(ci, zr,  cr * zi);
                cr = nr; ci = ni;
            }
        }
#pragma unroll
        for (int s = 0; s < 3; ++s) {                 // 7-shfl halving on v[8]
            const int  half = 4 >> s;
            const bool up   = (lane >> s) & 1;
#pragma unroll
            for (int k = 0; k < half; ++k) {
                float send = up ? v[k] : v[k + half];
                float recv = __shfl_xor_sync(0xffffffffu, send, 1 << s);
                v[k] = (up ? v[k + half] : v[k]) + recv;
            }
        }
        v[0] += __shfl_xor_sync(0xffffffffu, v[0], 8);    // fold lane groups
        v[0] += __shfl_xor_sync(0xffffffffu, v[0], 16);
        if (lane < 8) {
            const int r = __brev(lane) >> 29;         // bitrev3 -> accumulator idx
            const int m = 4 * w + (r >> 1);
            g_part[b][(r & 1) * NMODES + m][rank] = v[0];
        }
    }

    // ---- cluster rendezvous (8 CTAs) -------------------------------------
    __threadfence();
    asm volatile("barrier.cluster.arrive.aligned;" ::: "memory");
    asm volatile("barrier.cluster.wait.aligned;"   ::: "memory");

    // ---- reduce 8 rank-partials ------------------------------------------
    if (tid < 2 * NMODES) {
        float4 u0 = __ldcg((const float4*)&g_part[b][tid][0]);
        float4 u1 = __ldcg((const float4*)&g_part[b][tid][4]);
        rowsum[tid] = ((u0.x + u0.y) + (u0.z + u0.w))
                    + ((u1.x + u1.y) + (u1.z + u1.w));
    }
    __syncthreads();

    // ---- spectral multiplier tables --------------------------------------
    if (tid < NMODES) {
        const int m = tid;
        const double TWO_PI_D = 6.283185307179586476925286766559;
        const double taud  = 12.0 / ((TWO_PI_D * 2001.0) * (TWO_PI_D * 2001.0));
        const float TAUF     = (float)taud;
        const float SQPIOTAU = (float)sqrt(3.14159265358979323846 / taud);
        const float s_   = sigma_var[0];
        const float q0   = 25.f * shift0[0] * shift0[0];
        const float q1   = 25.f * shift1[0] * shift1[0];
        const float FOURPI = 12.566370614359172f;
        float kk = TWO_PI_F * (float)m;
        float K2 = kk * kk;
        float fold = (m == 0) ? 1.f : 2.f;
        float base0 = fold * (-amp0[0]) * FOURPI / (K2 + q0);
        float inv  = 1.f / (K2 + q1);
        float base1 = fold * amp1[0] * FOURPI * inv * inv;
        float eg = __expf(-0.5f * s_ * s_ * K2);
        float eU = TWO_PI_F * eg;                     // window x deconv = 2*pi exactly
        float eV = SQPIOTAU * __expf((TAUF - 0.5f * s_ * s_) * K2);
        tabU[m] = make_float4(rowsum[m], rowsum[NMODES + m], base0 * eU, base1 * eU);
        tabV[m] = make_float2(base0 * eV, base1 * eV);
    }
    __syncthreads();

    // ---- edge field: 16 slots x 4 threads (WHOLE warps 0,1; 12 slots used)
    if (tid < 64) {
        const int e = tid >> 2;                       // 0..15 (12 used)
        const int q = tid & 3;
        const int g = (e < 6) ? e : ((e < 12) ? (1995 + (e - 6)) : 1000);

        const float C_HI = (float)(1.0 / 2001.0);
        const float C_LO = (float)(1.0 / 2001.0 - (double)((float)(1.0 / 2001.0)));
        const float gf     = (float)g;
        const float phi_hi = gf * C_HI;
        const float phi_lo = fmaf(gf, C_HI, -phi_hi) + gf * C_LO;

        float sw_, cw_;
        __sincosf(TWO_PI_F * ((phi_hi - rintf(phi_hi)) + phi_lo), &sw_, &cw_);
        float zr, zi;                                 // base at m0 = 12q (exact)
        if (q == 0) { zr = 1.f; zi = 0.f; }
        else {
            float m0f = (float)(12 * q);
            float hi2 = m0f * phi_hi;
            float lo2 = fmaf(m0f, phi_hi, -hi2);
            float f   = (hi2 - rintf(hi2)) + (lo2 + m0f * phi_lo);
            __sincosf(TWO_PI_F * (f - rintf(f)), &zi, &zr);
        }
        float acc0 = 0.f, acc1 = 0.f;
#pragma unroll
        for (int j = 0; j < 12; ++j) {
            const int m = 12 * q + j;
            float4 t4 = tabU[m];                      // A, B
            float2 v2 = tabV[m];                      // V0, V1
            float tt = fmaf(t4.x, zr, t4.y * zi);
            acc0 = fmaf(v2.x, tt, acc0);
            acc1 = fmaf(v2.y, tt, acc1);
            float nzr = fmaf(zr, cw_, -zi * sw_);
            float nzi = fmaf(zi, cw_,  zr * sw_);
            zr = nzr; zi = nzi;
        }
        acc0 += __shfl_xor_sync(0xffffffffu, acc0, 1);
        acc0 += __shfl_xor_sync(0xffffffffu, acc0, 2);
        acc1 += __shfl_xor_sync(0xffffffffu, acc1, 1);
        acc1 += __shfl_xor_sync(0xffffffffu, acc1, 2);
        if (q == 0 && e < 12) { sf0[e] = acc0; sf1[e] = acc1; }
    }
    __syncthreads();

    // ---- output: 4 threads/particle, 12-mode chains ----------------------
    {
        const int s  = tid >> 2;                      // 0..127
        const int q  = tid & 3;
        const int p  = b * NPART + rank * 128 + s;
        const float xv = x[p];

        float zr, zi;                                 // z = e^{2*pi*i*x}
        __sincosf(TWO_PI_F * (xv - rintf(xv)), &zi, &zr);
        // base = z^{12q} via FMA: z12 = z8*z4; z24 = z12^2; select by q bits
        float z2r, z2i, z4r, z4i, z8r, z8i, z12r, z12i, z24r, z24i;
        CSQ(z2r, z2i, zr,  zi);
        CSQ(z4r, z4i, z2r, z2i);
        CSQ(z8r, z8i, z4r, z4i);
        CMUL(z12r, z12i, z8r, z8i, z4r, z4i);
        CSQ(z24r, z24i, z12r, z12i);
        float b1r = (q & 1) ? z12r : 1.f, b1i = (q & 1) ? z12i : 0.f;
        float b2r = (q & 2) ? z24r : 1.f, b2i = (q & 2) ? z24i : 0.f;
        float cr, ci;
        CMUL(cr, ci, b1r, b1i, b2r, b2i);

        float acc0 = 0.f, acc1 = 0.f;
#pragma unroll
        for (int j = 0; j < 12; ++j) {
            float4 t4 = tabU[12 * q + j];
            float tt = fmaf(t4.x, cr, t4.y * ci);
            acc0 = fmaf(t4.z, tt, acc0);
            acc1 = fmaf(t4.w, tt, acc1);
            float nr = fmaf(cr, zr, -ci * zi);
            float ni = fmaf(ci, zr,  cr * zi);
            cr = nr; ci = ni;
        }
        acc0 += __shfl_xor_sync(0xffffffffu, acc0, 1);
        acc0 += __shfl_xor_sync(0xffffffffu, acc0, 2);
        acc1 += __shfl_xor_sync(0xffffffffu, acc1, 1);
        acc1 += __shfl_xor_sync(0xffffffffu, acc1, 2);

        if (q == 0) {
            // wrap corrections (reference clamps; Poisson periodizes)
            const double TWO_PI_D = 6.283185307179586476925286766559;
            const float TAUF    = (float)(12.0 / ((TWO_PI_D * 2001.0) * (TWO_PI_D * 2001.0)));
            const float inv4tau = 1.f / (4.f * TAUF);
            const float invN    = (float)(1.0 / 2001.0);
            const int m0 = __float2int_rn(xv * 2001.0f);
            if (m0 <= 6) {
#pragma unroll
                for (int j = 1; j <= 6; ++j) {        // phantom n = -j -> grid 2001-j
                    float d = xv + (float)j * invN;
                    float wgt = invN * __expf(-d * d * inv4tau);
                    acc0 -= wgt * sf0[12 - j];
                    acc1 -= wgt * sf1[12 - j];
                }
            }
            if (m0 >= 1994) {
#pragma unroll
                for (int j = 0; j <= 5; ++j) {        // phantom n = 2001+j -> grid j
                    float d = xv - 1.f - (float)j * invN;
                    float wgt = invN * __expf(-d * d * inv4tau);
                    acc0 -= wgt * sf0[j];
                    acc1 -= wgt * sf1[j];
                }
            }
            out[2 * p]     = acc0;
            out[2 * p + 1] = acc1;
        }
    }
}

// ---------------------------------------------------------------------------
extern "C" void kernel_launch(void* const* d_in, const int* in_sizes, int n_in,
                              void* d_out, int out_size)
{
    (void)in_sizes; (void)n_in; (void)out_size;
    k_fused<<<GRIDB, TPB>>>((const float*)d_in[0], (const float*)d_in[1],
                            (const float*)d_in[2], (const float*)d_in[3],
                            (const float*)d_in[4], (const float*)d_in[5],
                            (float*)d_out);
}